// round 2
// baseline (speedup 1.0000x reference)
#include <cuda_runtime.h>
#include <cstdint>

#define N_NODES     100000
#define OUT_F       16

// ---------------------------------------------------------------------------
// Kernel 1: zero the output (harness poisons d_out with 0xAA).
// ---------------------------------------------------------------------------
__global__ void __launch_bounds__(256)
zero_out_kernel(float4* __restrict__ out, int n4) {
    int stride = gridDim.x * blockDim.x;
    for (int i = blockIdx.x * blockDim.x + threadIdx.x; i < n4; i += stride)
        out[i] = make_float4(0.f, 0.f, 0.f, 0.f);
}

// ---------------------------------------------------------------------------
// Kernel 2: scatter-add. One thread per edge (grid-stride).
//   - coalesced int32 src load
//   - 4x float4 streaming loads of the 64B edge_w row (__ldcs: keep the
//     205MB stream out of L2 so the 6.4MB output stays resident for atomics)
//   - 4x red.global.add.v4.f32 (no-return vectorized L2 reduction, REDG)
// ---------------------------------------------------------------------------
__global__ void __launch_bounds__(256)
scatter_add_kernel(const int* __restrict__ src,
                   const float4* __restrict__ w,      // edge_w as [E][4] float4
                   float* __restrict__ out,           // [N][16]
                   int E) {
    int stride = gridDim.x * blockDim.x;
    for (int i = blockIdx.x * blockDim.x + threadIdx.x; i < E; i += stride) {
        int s = __ldg(src + i);

        const float4* row = w + (size_t)i * 4;
        float4 v0 = __ldcs(row + 0);
        float4 v1 = __ldcs(row + 1);
        float4 v2 = __ldcs(row + 2);
        float4 v3 = __ldcs(row + 3);

        float* base = out + (size_t)s * OUT_F;

        asm volatile("red.global.add.v4.f32 [%0], {%1,%2,%3,%4};"
                     :: "l"(base + 0), "f"(v0.x), "f"(v0.y), "f"(v0.z), "f"(v0.w) : "memory");
        asm volatile("red.global.add.v4.f32 [%0], {%1,%2,%3,%4};"
                     :: "l"(base + 4), "f"(v1.x), "f"(v1.y), "f"(v1.z), "f"(v1.w) : "memory");
        asm volatile("red.global.add.v4.f32 [%0], {%1,%2,%3,%4};"
                     :: "l"(base + 8), "f"(v2.x), "f"(v2.y), "f"(v2.z), "f"(v2.w) : "memory");
        asm volatile("red.global.add.v4.f32 [%0], {%1,%2,%3,%4};"
                     :: "l"(base + 12), "f"(v3.x), "f"(v3.y), "f"(v3.z), "f"(v3.w) : "memory");
    }
}

// ---------------------------------------------------------------------------
// kernel_launch
// Inputs (metadata order): edge [2, E] int32, edge_w [E, 16] f32, N, E, F
// ---------------------------------------------------------------------------
extern "C" void kernel_launch(void* const* d_in, const int* in_sizes, int n_in,
                              void* d_out, int out_size) {
    const int*    edge   = (const int*)d_in[0];      // [2, E]; row 0 = src
    const float4* edge_w = (const float4*)d_in[1];   // [E, 16] -> [E][4] float4
    float*        out    = (float*)d_out;            // [N, 16]

    const int E  = in_sizes[0] / 2;                  // edge has 2*E elements
    const int n4 = out_size / 4;                     // output float4 count

    {
        int threads = 256;
        int blocks = (n4 + threads - 1) / threads;
        if (blocks > 8192) blocks = 8192;
        zero_out_kernel<<<blocks, threads>>>((float4*)out, n4);
    }
    {
        int threads = 256;
        int blocks = (E + threads - 1) / threads;
        if (blocks > 65535) blocks = 65535;
        scatter_add_kernel<<<blocks, threads>>>(edge, edge_w, out, E);
    }
}

// round 3
// speedup vs baseline: 1.5756x; 1.5756x over previous
#include <cuda_runtime.h>
#include <cstdint>

#define OUT_F 16

// ---------------------------------------------------------------------------
// Kernel 1: zero the output (harness poisons d_out with 0xAA).
// ---------------------------------------------------------------------------
__global__ void __launch_bounds__(256)
zero_out_kernel(float4* __restrict__ out, int n4) {
    int stride = gridDim.x * blockDim.x;
    for (int i = blockIdx.x * blockDim.x + threadIdx.x; i < n4; i += stride)
        out[i] = make_float4(0.f, 0.f, 0.f, 0.f);
}

// ---------------------------------------------------------------------------
// Kernel 2: scatter-add, QUAD layout: 4 threads per edge, one float4 chunk
// per thread.
//   - streaming load w[t] is perfectly coalesced (128B per 8 lanes)
//   - the warp's single red.v4 instruction covers 8 edges, each edge's 4
//     lanes hitting one contiguous 64B of its output row -> ~1 L1tex
//     wavefront per edge instead of 4, and 64B-contiguous op groups at L2
//   - src[e] is read by 4 adjacent lanes (intra-line broadcast, free)
// ---------------------------------------------------------------------------
__global__ void __launch_bounds__(256)
scatter_add_quad(const int* __restrict__ src,
                 const float4* __restrict__ w,     // edge_w as [E*4] float4
                 float* __restrict__ out,          // [N][16]
                 int work)                         // work = 4*E
{
    int stride = gridDim.x * blockDim.x;
    for (int t = blockIdx.x * blockDim.x + threadIdx.x; t < work; t += stride) {
        int e = t >> 2;        // edge index
        int c = t & 3;         // chunk 0..3

        int s = __ldg(src + e);
        float4 v = __ldcs(w + t);   // w[e*4 + c] == w[t]

        float* dst = out + (size_t)s * OUT_F + c * 4;
        asm volatile("red.global.add.v4.f32 [%0], {%1,%2,%3,%4};"
                     :: "l"(dst), "f"(v.x), "f"(v.y), "f"(v.z), "f"(v.w)
                     : "memory");
    }
}

// ---------------------------------------------------------------------------
// kernel_launch
// Inputs (metadata order): edge [2, E] int32, edge_w [E, 16] f32, N, E, F
// ---------------------------------------------------------------------------
extern "C" void kernel_launch(void* const* d_in, const int* in_sizes, int n_in,
                              void* d_out, int out_size) {
    const int*    edge   = (const int*)d_in[0];      // [2, E]; row 0 = src
    const float4* edge_w = (const float4*)d_in[1];   // [E, 16] -> [4E] float4
    float*        out    = (float*)d_out;            // [N, 16]

    const int E    = in_sizes[0] / 2;                // edge has 2*E elements
    const int work = 4 * E;                          // 4 threads per edge
    const int n4   = out_size / 4;                   // output float4 count

    {
        int threads = 256;
        int blocks = (n4 + threads - 1) / threads;
        if (blocks > 8192) blocks = 8192;
        zero_out_kernel<<<blocks, threads>>>((float4*)out, n4);
    }
    {
        int threads = 256;
        int blocks = (work + threads - 1) / threads;   // 50000 for E=3.2M
        scatter_add_quad<<<blocks, threads>>>(edge, edge_w, out, work);
    }
}